// round 10
// baseline (speedup 1.0000x reference)
#include <cuda_runtime.h>
#include <cstdint>

#define BB 32
#define TT 4096
#define DD 64
#define HH 128
#define SS 64
#define FEPS 1e-10f

// ---------------- device scratch (no allocs allowed) ----------------
__device__ float2 g_em2[(size_t)BB * TT * 32];     // emission probs, paired states (32MB)
__device__ float2 g_alpha2[(size_t)BB * TT * 32];  // forward messages (32MB)
__device__ float2 g_beta2[(size_t)BB * TT * 32];   // backward messages (32MB)
__device__ float2 g_Afwd2[32 * 64];  // (A[i][2l], A[i][2l+1]) at [l][i]
__device__ float2 g_Abwd2[32 * 64];  // (A[2l][j], A[2l+1][j]) at [l][j]
__device__ float2 g_pi2[32];
__device__ float  g_partial[(size_t)BB * 256 * SS];  // per-warp-chunk marginal partials

// ---------------- f32x2 helpers (packed fp32 FMA; ptxas never emits from C++) ----
__device__ __forceinline__ unsigned long long dup2(float x) {
    unsigned long long r;
    asm("mov.b64 %0, {%1, %1};" : "=l"(r) : "f"(x));
    return r;
}
__device__ __forceinline__ void fma2(unsigned long long& d, unsigned long long a,
                                     unsigned long long b) {
    asm("fma.rn.f32x2 %0, %1, %2, %0;" : "+l"(d) : "l"(a), "l"(b));
}
__device__ __forceinline__ float2 unpk(unsigned long long v) {
    float2 r;
    asm("mov.b64 {%0, %1}, %2;" : "=f"(r.x), "=f"(r.y) : "l"(v));
    return r;
}

// =====================================================================
// 1) prep: transition softmax (+eps), packed A layouts, pi, durations
// =====================================================================
__global__ void prep_kernel(const float* __restrict__ logT,
                            const float* __restrict__ logInit,
                            const float* __restrict__ logR,
                            const float* __restrict__ logitP,
                            float* __restrict__ out_dur) {
    __shared__ float A[SS * SS];
    int tid = threadIdx.x;  // 64 threads
    {
        int i = tid;
        float row[SS];
        float m = -1e30f;
#pragma unroll
        for (int j = 0; j < SS; j++) {
            float v = (j == i) ? -1e10f : logT[i * SS + j];
            row[j] = v;
            m = fmaxf(m, v);
        }
        float s = 0.f;
#pragma unroll
        for (int j = 0; j < SS; j++) { row[j] = __expf(row[j] - m); s += row[j]; }
        float inv = 1.f / s;
#pragma unroll
        for (int j = 0; j < SS; j++) A[i * SS + j] = fmaf(row[j], inv, FEPS);
    }
    __syncthreads();
    if (tid < 32) {
        int l = tid;
#pragma unroll 4
        for (int i = 0; i < SS; i++) {
            g_Afwd2[l * 64 + i] = make_float2(A[i * SS + 2 * l], A[i * SS + 2 * l + 1]);
            g_Abwd2[l * 64 + i] = make_float2(A[(2 * l) * SS + i], A[(2 * l + 1) * SS + i]);
        }
    }
    if (tid == 0) {
        float m = -1e30f;
        for (int j = 0; j < SS; j++) m = fmaxf(m, logInit[j]);
        float e[SS];
        float s = 0.f;
        for (int j = 0; j < SS; j++) { e[j] = __expf(logInit[j] - m); s += e[j]; }
        float inv = 1.f / s;
        for (int j = 0; j < 32; j++)
            g_pi2[j] = make_float2(e[2 * j] * inv, e[2 * j + 1] * inv);
    }
    if (tid < SS) {
        float r = expf(logR[tid]);
        float p = 1.f / (1.f + expf(-logitP[tid]));
        out_dur[tid] = r * (1.f - p) / p;
    }
}

// =====================================================================
// 2) emission MLP: persistent blocks, weights in smem, 4-row blocking
// =====================================================================
__device__ __forceinline__ float4 relu4(float4 v) {
    return make_float4(fmaxf(v.x, 0.f), fmaxf(v.y, 0.f), fmaxf(v.z, 0.f), fmaxf(v.w, 0.f));
}

// smem layout (floats): W1 8192 | W2 16384 | W3 8192 | b1 128 | b2 128 | b3 64 | 8 warps x 1280
#define SM_FLOATS (33088 + 8 * 1280)

__global__ __launch_bounds__(256) void mlp_kernel(
    const float* __restrict__ obs,
    const float* __restrict__ W1, const float* __restrict__ b1,
    const float* __restrict__ W2, const float* __restrict__ b2,
    const float* __restrict__ W3, const float* __restrict__ b3) {
    extern __shared__ float sm[];
    float* W1s = sm;
    float* W2s = sm + 8192;
    float* W3s = sm + 24576;
    float* b1s = sm + 32768;
    float* b2s = sm + 32896;
    float* b3s = sm + 33024;
    float* wbuf = sm + 33088;

    int tid = threadIdx.x, w = tid >> 5, l = tid & 31;

    for (int i = tid; i < 8192 / 4; i += 256) ((float4*)W1s)[i] = ((const float4*)W1)[i];
    for (int i = tid; i < 16384 / 4; i += 256) ((float4*)W2s)[i] = ((const float4*)W2)[i];
    for (int i = tid; i < 8192 / 4; i += 256) ((float4*)W3s)[i] = ((const float4*)W3)[i];
    if (tid < 128) { b1s[tid] = b1[tid]; b2s[tid] = b2[tid]; }
    if (tid < 64) b3s[tid] = b3[tid];
    __syncthreads();

    float* xs = wbuf + w * 1280;  // 256 floats: 4 rows x 64
    float* h1 = xs + 256;         // 512 floats: 4 rows x 128
    float* h2 = h1 + 512;         // 512 floats

    const int nrb = (BB * TT) / 32;  // 4096 row-blocks of 32 rows
    for (int rb = blockIdx.x; rb < nrb; rb += gridDim.x) {
        int base = rb * 32 + w * 4;  // this warp's 4 rows
        const float4* ob = (const float4*)(obs + (size_t)base * DD);
        ((float4*)xs)[l] = ob[l];
        ((float4*)xs)[l + 32] = ob[l + 32];
        __syncwarp();

        // ---- layer 1: (4 x 64) @ (64 x 128), lane owns outputs 4l..4l+3 ----
        float4 a0 = ((const float4*)b1s)[l];
        float4 a1 = a0, a2 = a0, a3 = a0;
#pragma unroll 8
        for (int k = 0; k < DD; k++) {
            float4 wv = ((const float4*)W1s)[k * 32 + l];
            float x0 = xs[k], x1 = xs[64 + k], x2 = xs[128 + k], x3 = xs[192 + k];
            a0.x = fmaf(wv.x, x0, a0.x); a0.y = fmaf(wv.y, x0, a0.y);
            a0.z = fmaf(wv.z, x0, a0.z); a0.w = fmaf(wv.w, x0, a0.w);
            a1.x = fmaf(wv.x, x1, a1.x); a1.y = fmaf(wv.y, x1, a1.y);
            a1.z = fmaf(wv.z, x1, a1.z); a1.w = fmaf(wv.w, x1, a1.w);
            a2.x = fmaf(wv.x, x2, a2.x); a2.y = fmaf(wv.y, x2, a2.y);
            a2.z = fmaf(wv.z, x2, a2.z); a2.w = fmaf(wv.w, x2, a2.w);
            a3.x = fmaf(wv.x, x3, a3.x); a3.y = fmaf(wv.y, x3, a3.y);
            a3.z = fmaf(wv.z, x3, a3.z); a3.w = fmaf(wv.w, x3, a3.w);
        }
        ((float4*)h1)[l] = relu4(a0);
        ((float4*)h1)[32 + l] = relu4(a1);
        ((float4*)h1)[64 + l] = relu4(a2);
        ((float4*)h1)[96 + l] = relu4(a3);
        __syncwarp();

        // ---- layer 2: (4 x 128) @ (128 x 128) ----
        a0 = ((const float4*)b2s)[l];
        a1 = a0; a2 = a0; a3 = a0;
#pragma unroll 8
        for (int k = 0; k < HH; k++) {
            float4 wv = ((const float4*)W2s)[k * 32 + l];
            float x0 = h1[k], x1 = h1[128 + k], x2 = h1[256 + k], x3 = h1[384 + k];
            a0.x = fmaf(wv.x, x0, a0.x); a0.y = fmaf(wv.y, x0, a0.y);
            a0.z = fmaf(wv.z, x0, a0.z); a0.w = fmaf(wv.w, x0, a0.w);
            a1.x = fmaf(wv.x, x1, a1.x); a1.y = fmaf(wv.y, x1, a1.y);
            a1.z = fmaf(wv.z, x1, a1.z); a1.w = fmaf(wv.w, x1, a1.w);
            a2.x = fmaf(wv.x, x2, a2.x); a2.y = fmaf(wv.y, x2, a2.y);
            a2.z = fmaf(wv.z, x2, a2.z); a2.w = fmaf(wv.w, x2, a2.w);
            a3.x = fmaf(wv.x, x3, a3.x); a3.y = fmaf(wv.y, x3, a3.y);
            a3.z = fmaf(wv.z, x3, a3.z); a3.w = fmaf(wv.w, x3, a3.w);
        }
        ((float4*)h2)[l] = relu4(a0);
        ((float4*)h2)[32 + l] = relu4(a1);
        ((float4*)h2)[64 + l] = relu4(a2);
        ((float4*)h2)[96 + l] = relu4(a3);
        __syncwarp();

        // ---- layer 3: (4 x 128) @ (128 x 64), lane owns outputs 2l, 2l+1 ----
        float2 c0 = ((const float2*)b3s)[l];
        float2 c1 = c0, c2 = c0, c3 = c0;
#pragma unroll 8
        for (int k = 0; k < HH; k++) {
            float2 wv = ((const float2*)W3s)[k * 32 + l];
            float x0 = h2[k], x1 = h2[128 + k], x2 = h2[256 + k], x3 = h2[384 + k];
            c0.x = fmaf(wv.x, x0, c0.x); c0.y = fmaf(wv.y, x0, c0.y);
            c1.x = fmaf(wv.x, x1, c1.x); c1.y = fmaf(wv.y, x1, c1.y);
            c2.x = fmaf(wv.x, x2, c2.x); c2.y = fmaf(wv.y, x2, c2.y);
            c3.x = fmaf(wv.x, x3, c3.x); c3.y = fmaf(wv.y, x3, c3.y);
        }

        // ---- softmax over 64 states (interleaved butterflies for ILP) ----
        float m0 = fmaxf(c0.x, c0.y), m1 = fmaxf(c1.x, c1.y);
        float m2 = fmaxf(c2.x, c2.y), m3 = fmaxf(c3.x, c3.y);
#pragma unroll
        for (int d = 16; d; d >>= 1) {
            m0 = fmaxf(m0, __shfl_xor_sync(0xffffffffu, m0, d));
            m1 = fmaxf(m1, __shfl_xor_sync(0xffffffffu, m1, d));
            m2 = fmaxf(m2, __shfl_xor_sync(0xffffffffu, m2, d));
            m3 = fmaxf(m3, __shfl_xor_sync(0xffffffffu, m3, d));
        }
        float e00 = __expf(c0.x - m0), e01 = __expf(c0.y - m0);
        float e10 = __expf(c1.x - m1), e11 = __expf(c1.y - m1);
        float e20 = __expf(c2.x - m2), e21 = __expf(c2.y - m2);
        float e30 = __expf(c3.x - m3), e31 = __expf(c3.y - m3);
        float s0 = e00 + e01, s1 = e10 + e11, s2 = e20 + e21, s3 = e30 + e31;
#pragma unroll
        for (int d = 16; d; d >>= 1) {
            s0 += __shfl_xor_sync(0xffffffffu, s0, d);
            s1 += __shfl_xor_sync(0xffffffffu, s1, d);
            s2 += __shfl_xor_sync(0xffffffffu, s2, d);
            s3 += __shfl_xor_sync(0xffffffffu, s3, d);
        }
        float i0 = 1.f / s0, i1 = 1.f / s1, i2 = 1.f / s2, i3 = 1.f / s3;
        g_em2[(size_t)(base + 0) * 32 + l] = make_float2(e00 * i0, e01 * i0);
        g_em2[(size_t)(base + 1) * 32 + l] = make_float2(e10 * i1, e11 * i1);
        g_em2[(size_t)(base + 2) * 32 + l] = make_float2(e20 * i2, e21 * i2);
        g_em2[(size_t)(base + 3) * 32 + l] = make_float2(e30 * i3, e31 * i3);
    }
}

// =====================================================================
// 3) recursions: one warp per (batch, direction); A column-pairs in regs,
//    duplicated-pair shared buffer, fma.rn.f32x2 inner loop,
//    renorm every 4 steps (scales cancel in gamma; LL tracks log-scale)
// =====================================================================
__global__ __launch_bounds__(32) void recur_kernel(float* __restrict__ d_ll) {
    int id = blockIdx.x;  // 64 = 32 batches x 2 directions
    int b = id >> 1;
    bool bwd = (id & 1) != 0;
    int l = threadIdx.x;

    __shared__ __align__(16) unsigned long long buf[2][64];

    unsigned long long cp[64];
    const unsigned long long* M =
        (const unsigned long long*)(bwd ? g_Abwd2 : g_Afwd2) + (size_t)l * 64;
#pragma unroll
    for (int i = 0; i < 64; i++) cp[i] = M[i];

    const float2* E = g_em2 + (size_t)b * TT * 32 + l;

    if (!bwd) {
        float2* AL = g_alpha2 + (size_t)b * TT * 32 + l;
        float2 pp = g_pi2[l];
        float2 e = E[0];
        float a0 = pp.x * e.x, a1 = pp.y * e.y;  // t=0: NO eps (matches reference)
        AL[0] = make_float2(a0, a1);
        ((ulonglong2*)buf[0])[l] = make_ulonglong2(dup2(a0), dup2(a1));
        __syncwarp();
        double c = 0.0;
        float2 en = E[32];
        for (int t = 1; t < TT; t++) {
            e = en;
            int tn = (t + 1 < TT) ? (t + 1) : (TT - 1);
            en = E[(size_t)tn * 32];
            unsigned long long acc = 0ull;
            const ulonglong2* bp = (const ulonglong2*)buf[(t - 1) & 1];
#pragma unroll
            for (int i = 0; i < 32; i++) {
                ulonglong2 v = bp[i];
                fma2(acc, cp[2 * i], v.x);
                fma2(acc, cp[2 * i + 1], v.y);
            }
            float2 s = unpk(acc);
            a0 = s.x * (e.x + FEPS);
            a1 = s.y * (e.y + FEPS);
            AL[(size_t)t * 32] = make_float2(a0, a1);  // per-t scale arbitrary
            if ((t & 3) == 3) {
                float sum = a0 + a1;
#pragma unroll
                for (int d = 16; d; d >>= 1) sum += __shfl_xor_sync(0xffffffffu, sum, d);
                float inv = 1.f / sum;
                a0 *= inv; a1 *= inv;
                c += (double)__logf(sum);
            }
            ((ulonglong2*)buf[t & 1])[l] = make_ulonglong2(dup2(a0), dup2(a1));
            __syncwarp();
        }
        float sum = a0 + a1;
#pragma unroll
        for (int d = 16; d; d >>= 1) sum += __shfl_xor_sync(0xffffffffu, sum, d);
        if (l == 0) d_ll[b] = __logf(sum) + (float)c;
    } else {
        float2* BL = g_beta2 + (size_t)b * TT * 32 + l;
        float b0 = 1.f, b1 = 1.f;
        BL[(size_t)(TT - 1) * 32] = make_float2(1.f, 1.f);
        float2 e = E[(size_t)(TT - 1) * 32];  // em_{t+1} for t = TT-2
        for (int t = TT - 2; t >= 0; t--) {
            float v0 = b0 * (e.x + FEPS), v1 = b1 * (e.y + FEPS);
            ((ulonglong2*)buf[t & 1])[l] = make_ulonglong2(dup2(v0), dup2(v1));
            __syncwarp();
            int tp = (t > 0) ? t : 0;
            e = E[(size_t)tp * 32];  // prefetch em_t for next iteration
            unsigned long long acc = 0ull;
            const ulonglong2* bp = (const ulonglong2*)buf[t & 1];
#pragma unroll
            for (int i = 0; i < 32; i++) {
                ulonglong2 v = bp[i];
                fma2(acc, cp[2 * i], v.x);
                fma2(acc, cp[2 * i + 1], v.y);
            }
            float2 s = unpk(acc);
            b0 = s.x; b1 = s.y;
            BL[(size_t)t * 32] = make_float2(b0, b1);
            if ((t & 3) == 0) {
                float sum = b0 + b1;
#pragma unroll
                for (int d = 16; d; d >>= 1) sum += __shfl_xor_sync(0xffffffffu, sum, d);
                float inv = 1.f / sum;
                b0 *= inv; b1 *= inv;
            }
        }
    }
}

// =====================================================================
// 4) gamma + deterministic marginal partials (warp per row)
// =====================================================================
__global__ __launch_bounds__(256) void gamma_kernel(float* __restrict__ outp) {
    int w = threadIdx.x >> 5, l = threadIdx.x & 31;
    int R0 = blockIdx.x * 128;  // grid 1024; 128 rows/block; never straddles b
    int rowbase = R0 + w * 16;
    float2* O2 = (float2*)outp;
    float m0 = 0.f, m1 = 0.f;
    for (int i = 0; i < 16; i++) {
        size_t row = (size_t)(rowbase + i);
        float2 a = g_alpha2[row * 32 + l];
        float2 bb = g_beta2[row * 32 + l];
        float gg0 = a.x * bb.x, gg1 = a.y * bb.y;
        float s = gg0 + gg1;
#pragma unroll
        for (int d = 16; d; d >>= 1) s += __shfl_xor_sync(0xffffffffu, s, d);
        float inv = 1.f / s;
        gg0 *= inv; gg1 *= inv;
        O2[row * 32 + l] = make_float2(gg0, gg1);
        m0 += gg0; m1 += gg1;
    }
    int b = R0 >> 12;                       // / 4096
    int chunk = ((R0 & 4095) >> 4) + w;     // [0, 256)
    float* P = g_partial + ((size_t)b * 256 + chunk) * SS;
    P[2 * l] = m0;
    P[2 * l + 1] = m1;
}

// fixed-order reduction over 256 partials per (b, s): deterministic
__global__ void fin_kernel(float* __restrict__ out_marg) {
    int gid = blockIdx.x * 256 + threadIdx.x;  // grid 8 -> 2048 = B*S
    int b = gid >> 6, s = gid & 63;
    const float* P = g_partial + (size_t)b * 256 * SS + s;
    float acc = 0.f;
#pragma unroll 8
    for (int k = 0; k < 256; k++) acc += P[k * SS];
    out_marg[gid] = acc * (1.f / TT);
}

// =====================================================================
extern "C" void kernel_launch(void* const* d_in, const int* in_sizes, int n_in,
                              void* d_out, int out_size) {
    const float* obs     = (const float*)d_in[0];
    const float* W1      = (const float*)d_in[1];
    const float* b1      = (const float*)d_in[2];
    const float* W2      = (const float*)d_in[3];
    const float* b2      = (const float*)d_in[4];
    const float* W3      = (const float*)d_in[5];
    const float* b3      = (const float*)d_in[6];
    const float* logT    = (const float*)d_in[7];
    const float* logInit = (const float*)d_in[8];
    const float* logR    = (const float*)d_in[9];
    const float* logitP  = (const float*)d_in[10];

    float* out = (float*)d_out;
    float* out_sp   = out;                                  // (B,T,S) = 8388608
    float* out_marg = out + (size_t)BB * TT * SS;           // (B,S)   = 2048
    float* out_dur  = out_marg + BB * SS;                   // (S,)    = 64
    float* out_ll   = out_dur + SS;                         // (B,)    = 32

    int smem = SM_FLOATS * 4;  // 173,312 B
    cudaFuncSetAttribute(mlp_kernel, cudaFuncAttributeMaxDynamicSharedMemorySize, smem);

    prep_kernel<<<1, 64>>>(logT, logInit, logR, logitP, out_dur);
    mlp_kernel<<<148, 256, smem>>>(obs, W1, b1, W2, b2, W3, b3);
    recur_kernel<<<64, 32>>>(out_ll);
    gamma_kernel<<<(BB * TT) / 128, 256>>>(out_sp);
    fin_kernel<<<8, 256>>>(out_marg);
}

// round 13
// speedup vs baseline: 1.0999x; 1.0999x over previous
#include <cuda_runtime.h>
#include <cstdint>

#define BB 32
#define TT 4096
#define DD 64
#define HH 128
#define SS 64
#define FEPS 1e-10f

// ---------------- device scratch (no allocs allowed) ----------------
__device__ float2 g_em2[(size_t)BB * TT * 32];     // emission probs, paired states (32MB)
__device__ float2 g_alpha2[(size_t)BB * TT * 32];  // forward messages (32MB)
__device__ float2 g_beta2[(size_t)BB * TT * 32];   // backward messages (32MB)
__device__ float2 g_Afwd2[32 * 64];  // (A[i][2l], A[i][2l+1]) at [l][i]
__device__ float2 g_Abwd2[32 * 64];  // (A[2l][j], A[2l+1][j]) at [l][j]
__device__ float2 g_pi2[32];
__device__ float  g_partial[(size_t)BB * 256 * SS];  // per-warp-chunk marginal partials

// ---------------- f32x2 helpers (packed fp32 FMA; ptxas never emits from C++) ----
__device__ __forceinline__ unsigned long long dup2(float x) {
    unsigned long long r;
    asm("mov.b64 %0, {%1, %1};" : "=l"(r) : "f"(x));
    return r;
}
__device__ __forceinline__ void fma2(unsigned long long& d, unsigned long long a,
                                     unsigned long long b) {
    asm("fma.rn.f32x2 %0, %1, %2, %0;" : "+l"(d) : "l"(a), "l"(b));
}
__device__ __forceinline__ float2 unpk(unsigned long long v) {
    float2 r;
    asm("mov.b64 {%0, %1}, %2;" : "=f"(r.x), "=f"(r.y) : "l"(v));
    return r;
}

// =====================================================================
// 1) prep: transition softmax (+eps), packed A layouts, pi, durations
// =====================================================================
__global__ void prep_kernel(const float* __restrict__ logT,
                            const float* __restrict__ logInit,
                            const float* __restrict__ logR,
                            const float* __restrict__ logitP,
                            float* __restrict__ out_dur) {
    __shared__ float A[SS * SS];
    int tid = threadIdx.x;  // 64 threads
    {
        int i = tid;
        float row[SS];
        float m = -1e30f;
#pragma unroll
        for (int j = 0; j < SS; j++) {
            float v = (j == i) ? -1e10f : logT[i * SS + j];
            row[j] = v;
            m = fmaxf(m, v);
        }
        float s = 0.f;
#pragma unroll
        for (int j = 0; j < SS; j++) { row[j] = __expf(row[j] - m); s += row[j]; }
        float inv = 1.f / s;
#pragma unroll
        for (int j = 0; j < SS; j++) A[i * SS + j] = fmaf(row[j], inv, FEPS);
    }
    __syncthreads();
    if (tid < 32) {
        int l = tid;
#pragma unroll 4
        for (int i = 0; i < SS; i++) {
            g_Afwd2[l * 64 + i] = make_float2(A[i * SS + 2 * l], A[i * SS + 2 * l + 1]);
            g_Abwd2[l * 64 + i] = make_float2(A[(2 * l) * SS + i], A[(2 * l + 1) * SS + i]);
        }
    }
    if (tid == 0) {
        float m = -1e30f;
        for (int j = 0; j < SS; j++) m = fmaxf(m, logInit[j]);
        float e[SS];
        float s = 0.f;
        for (int j = 0; j < SS; j++) { e[j] = __expf(logInit[j] - m); s += e[j]; }
        float inv = 1.f / s;
        for (int j = 0; j < 32; j++)
            g_pi2[j] = make_float2(e[2 * j] * inv, e[2 * j + 1] * inv);
    }
    if (tid < SS) {
        float r = expf(logR[tid]);
        float p = 1.f / (1.f + expf(-logitP[tid]));
        out_dur[tid] = r * (1.f - p) / p;
    }
}

// =====================================================================
// 2) emission MLP: persistent blocks, weights in smem, 4-row blocking
// =====================================================================
__device__ __forceinline__ float4 relu4(float4 v) {
    return make_float4(fmaxf(v.x, 0.f), fmaxf(v.y, 0.f), fmaxf(v.z, 0.f), fmaxf(v.w, 0.f));
}

// smem layout (floats): W1 8192 | W2 16384 | W3 8192 | b1 128 | b2 128 | b3 64 | 8 warps x 1280
#define SM_FLOATS (33088 + 8 * 1280)

__global__ __launch_bounds__(256) void mlp_kernel(
    const float* __restrict__ obs,
    const float* __restrict__ W1, const float* __restrict__ b1,
    const float* __restrict__ W2, const float* __restrict__ b2,
    const float* __restrict__ W3, const float* __restrict__ b3) {
    extern __shared__ float sm[];
    float* W1s = sm;
    float* W2s = sm + 8192;
    float* W3s = sm + 24576;
    float* b1s = sm + 32768;
    float* b2s = sm + 32896;
    float* b3s = sm + 33024;
    float* wbuf = sm + 33088;

    int tid = threadIdx.x, w = tid >> 5, l = tid & 31;

    for (int i = tid; i < 8192 / 4; i += 256) ((float4*)W1s)[i] = ((const float4*)W1)[i];
    for (int i = tid; i < 16384 / 4; i += 256) ((float4*)W2s)[i] = ((const float4*)W2)[i];
    for (int i = tid; i < 8192 / 4; i += 256) ((float4*)W3s)[i] = ((const float4*)W3)[i];
    if (tid < 128) { b1s[tid] = b1[tid]; b2s[tid] = b2[tid]; }
    if (tid < 64) b3s[tid] = b3[tid];
    __syncthreads();

    float* xs = wbuf + w * 1280;  // 256 floats: 4 rows x 64
    float* h1 = xs + 256;         // 512 floats: 4 rows x 128
    float* h2 = h1 + 512;         // 512 floats

    const int nrb = (BB * TT) / 32;  // 4096 row-blocks of 32 rows
    for (int rb = blockIdx.x; rb < nrb; rb += gridDim.x) {
        int base = rb * 32 + w * 4;  // this warp's 4 rows
        const float4* ob = (const float4*)(obs + (size_t)base * DD);
        ((float4*)xs)[l] = ob[l];
        ((float4*)xs)[l + 32] = ob[l + 32];
        __syncwarp();

        // ---- layer 1: (4 x 64) @ (64 x 128), lane owns outputs 4l..4l+3 ----
        float4 a0 = ((const float4*)b1s)[l];
        float4 a1 = a0, a2 = a0, a3 = a0;
#pragma unroll 8
        for (int k = 0; k < DD; k++) {
            float4 wv = ((const float4*)W1s)[k * 32 + l];
            float x0 = xs[k], x1 = xs[64 + k], x2 = xs[128 + k], x3 = xs[192 + k];
            a0.x = fmaf(wv.x, x0, a0.x); a0.y = fmaf(wv.y, x0, a0.y);
            a0.z = fmaf(wv.z, x0, a0.z); a0.w = fmaf(wv.w, x0, a0.w);
            a1.x = fmaf(wv.x, x1, a1.x); a1.y = fmaf(wv.y, x1, a1.y);
            a1.z = fmaf(wv.z, x1, a1.z); a1.w = fmaf(wv.w, x1, a1.w);
            a2.x = fmaf(wv.x, x2, a2.x); a2.y = fmaf(wv.y, x2, a2.y);
            a2.z = fmaf(wv.z, x2, a2.z); a2.w = fmaf(wv.w, x2, a2.w);
            a3.x = fmaf(wv.x, x3, a3.x); a3.y = fmaf(wv.y, x3, a3.y);
            a3.z = fmaf(wv.z, x3, a3.z); a3.w = fmaf(wv.w, x3, a3.w);
        }
        ((float4*)h1)[l] = relu4(a0);
        ((float4*)h1)[32 + l] = relu4(a1);
        ((float4*)h1)[64 + l] = relu4(a2);
        ((float4*)h1)[96 + l] = relu4(a3);
        __syncwarp();

        // ---- layer 2: (4 x 128) @ (128 x 128) ----
        a0 = ((const float4*)b2s)[l];
        a1 = a0; a2 = a0; a3 = a0;
#pragma unroll 8
        for (int k = 0; k < HH; k++) {
            float4 wv = ((const float4*)W2s)[k * 32 + l];
            float x0 = h1[k], x1 = h1[128 + k], x2 = h1[256 + k], x3 = h1[384 + k];
            a0.x = fmaf(wv.x, x0, a0.x); a0.y = fmaf(wv.y, x0, a0.y);
            a0.z = fmaf(wv.z, x0, a0.z); a0.w = fmaf(wv.w, x0, a0.w);
            a1.x = fmaf(wv.x, x1, a1.x); a1.y = fmaf(wv.y, x1, a1.y);
            a1.z = fmaf(wv.z, x1, a1.z); a1.w = fmaf(wv.w, x1, a1.w);
            a2.x = fmaf(wv.x, x2, a2.x); a2.y = fmaf(wv.y, x2, a2.y);
            a2.z = fmaf(wv.z, x2, a2.z); a2.w = fmaf(wv.w, x2, a2.w);
            a3.x = fmaf(wv.x, x3, a3.x); a3.y = fmaf(wv.y, x3, a3.y);
            a3.z = fmaf(wv.z, x3, a3.z); a3.w = fmaf(wv.w, x3, a3.w);
        }
        ((float4*)h2)[l] = relu4(a0);
        ((float4*)h2)[32 + l] = relu4(a1);
        ((float4*)h2)[64 + l] = relu4(a2);
        ((float4*)h2)[96 + l] = relu4(a3);
        __syncwarp();

        // ---- layer 3: (4 x 128) @ (128 x 64), lane owns outputs 2l, 2l+1 ----
        float2 c0 = ((const float2*)b3s)[l];
        float2 c1 = c0, c2 = c0, c3 = c0;
#pragma unroll 8
        for (int k = 0; k < HH; k++) {
            float2 wv = ((const float2*)W3s)[k * 32 + l];
            float x0 = h2[k], x1 = h2[128 + k], x2 = h2[256 + k], x3 = h2[384 + k];
            c0.x = fmaf(wv.x, x0, c0.x); c0.y = fmaf(wv.y, x0, c0.y);
            c1.x = fmaf(wv.x, x1, c1.x); c1.y = fmaf(wv.y, x1, c1.y);
            c2.x = fmaf(wv.x, x2, c2.x); c2.y = fmaf(wv.y, x2, c2.y);
            c3.x = fmaf(wv.x, x3, c3.x); c3.y = fmaf(wv.y, x3, c3.y);
        }

        // ---- softmax over 64 states (interleaved butterflies for ILP) ----
        float m0 = fmaxf(c0.x, c0.y), m1 = fmaxf(c1.x, c1.y);
        float m2 = fmaxf(c2.x, c2.y), m3 = fmaxf(c3.x, c3.y);
#pragma unroll
        for (int d = 16; d; d >>= 1) {
            m0 = fmaxf(m0, __shfl_xor_sync(0xffffffffu, m0, d));
            m1 = fmaxf(m1, __shfl_xor_sync(0xffffffffu, m1, d));
            m2 = fmaxf(m2, __shfl_xor_sync(0xffffffffu, m2, d));
            m3 = fmaxf(m3, __shfl_xor_sync(0xffffffffu, m3, d));
        }
        float e00 = __expf(c0.x - m0), e01 = __expf(c0.y - m0);
        float e10 = __expf(c1.x - m1), e11 = __expf(c1.y - m1);
        float e20 = __expf(c2.x - m2), e21 = __expf(c2.y - m2);
        float e30 = __expf(c3.x - m3), e31 = __expf(c3.y - m3);
        float s0 = e00 + e01, s1 = e10 + e11, s2 = e20 + e21, s3 = e30 + e31;
#pragma unroll
        for (int d = 16; d; d >>= 1) {
            s0 += __shfl_xor_sync(0xffffffffu, s0, d);
            s1 += __shfl_xor_sync(0xffffffffu, s1, d);
            s2 += __shfl_xor_sync(0xffffffffu, s2, d);
            s3 += __shfl_xor_sync(0xffffffffu, s3, d);
        }
        float i0 = 1.f / s0, i1 = 1.f / s1, i2 = 1.f / s2, i3 = 1.f / s3;
        g_em2[(size_t)(base + 0) * 32 + l] = make_float2(e00 * i0, e01 * i0);
        g_em2[(size_t)(base + 1) * 32 + l] = make_float2(e10 * i1, e11 * i1);
        g_em2[(size_t)(base + 2) * 32 + l] = make_float2(e20 * i2, e21 * i2);
        g_em2[(size_t)(base + 3) * 32 + l] = make_float2(e30 * i3, e31 * i3);
    }
}

// =====================================================================
// 3) recursions: one warp per (batch, direction); A column-pairs in regs,
//    duplicated-pair shared buffer, fma.rn.f32x2 inner loop,
//    renorm every 4 steps (scales cancel in gamma; LL tracks log-scale)
// =====================================================================
__global__ __launch_bounds__(32) void recur_kernel(float* __restrict__ d_ll) {
    int id = blockIdx.x;  // 64 = 32 batches x 2 directions
    int b = id >> 1;
    bool bwd = (id & 1) != 0;
    int l = threadIdx.x;

    __shared__ __align__(16) unsigned long long buf[2][64];

    unsigned long long cp[64];
    const unsigned long long* M =
        (const unsigned long long*)(bwd ? g_Abwd2 : g_Afwd2) + (size_t)l * 64;
#pragma unroll
    for (int i = 0; i < 64; i++) cp[i] = M[i];

    const float2* E = g_em2 + (size_t)b * TT * 32 + l;

    if (!bwd) {
        float2* AL = g_alpha2 + (size_t)b * TT * 32 + l;
        float2 pp = g_pi2[l];
        float2 e = E[0];
        float a0 = pp.x * e.x, a1 = pp.y * e.y;  // t=0: NO eps (matches reference)
        AL[0] = make_float2(a0, a1);
        ((ulonglong2*)buf[0])[l] = make_ulonglong2(dup2(a0), dup2(a1));
        __syncwarp();
        double c = 0.0;
        float2 en = E[32];
        for (int t = 1; t < TT; t++) {
            e = en;
            int tn = (t + 1 < TT) ? (t + 1) : (TT - 1);
            en = E[(size_t)tn * 32];
            unsigned long long acc = 0ull;
            const ulonglong2* bp = (const ulonglong2*)buf[(t - 1) & 1];
#pragma unroll
            for (int i = 0; i < 32; i++) {
                ulonglong2 v = bp[i];
                fma2(acc, cp[2 * i], v.x);
                fma2(acc, cp[2 * i + 1], v.y);
            }
            float2 s = unpk(acc);
            a0 = s.x * (e.x + FEPS);
            a1 = s.y * (e.y + FEPS);
            AL[(size_t)t * 32] = make_float2(a0, a1);  // per-t scale arbitrary
            if ((t & 3) == 3) {
                float sum = a0 + a1;
#pragma unroll
                for (int d = 16; d; d >>= 1) sum += __shfl_xor_sync(0xffffffffu, sum, d);
                float inv = 1.f / sum;
                a0 *= inv; a1 *= inv;
                c += (double)__logf(sum);
            }
            ((ulonglong2*)buf[t & 1])[l] = make_ulonglong2(dup2(a0), dup2(a1));
            __syncwarp();
        }
        float sum = a0 + a1;
#pragma unroll
        for (int d = 16; d; d >>= 1) sum += __shfl_xor_sync(0xffffffffu, sum, d);
        if (l == 0) d_ll[b] = __logf(sum) + (float)c;
    } else {
        float2* BL = g_beta2 + (size_t)b * TT * 32 + l;
        float b0 = 1.f, b1 = 1.f;
        BL[(size_t)(TT - 1) * 32] = make_float2(1.f, 1.f);
        float2 e = E[(size_t)(TT - 1) * 32];  // em_{t+1} for t = TT-2
        for (int t = TT - 2; t >= 0; t--) {
            float v0 = b0 * (e.x + FEPS), v1 = b1 * (e.y + FEPS);
            ((ulonglong2*)buf[t & 1])[l] = make_ulonglong2(dup2(v0), dup2(v1));
            __syncwarp();
            int tp = (t > 0) ? t : 0;
            e = E[(size_t)tp * 32];  // prefetch em_t for next iteration
            unsigned long long acc = 0ull;
            const ulonglong2* bp = (const ulonglong2*)buf[t & 1];
#pragma unroll
            for (int i = 0; i < 32; i++) {
                ulonglong2 v = bp[i];
                fma2(acc, cp[2 * i], v.x);
                fma2(acc, cp[2 * i + 1], v.y);
            }
            float2 s = unpk(acc);
            b0 = s.x; b1 = s.y;
            BL[(size_t)t * 32] = make_float2(b0, b1);
            if ((t & 3) == 0) {
                float sum = b0 + b1;
#pragma unroll
                for (int d = 16; d; d >>= 1) sum += __shfl_xor_sync(0xffffffffu, sum, d);
                float inv = 1.f / sum;
                b0 *= inv; b1 *= inv;
            }
        }
    }
}

// =====================================================================
// 4) gamma + deterministic marginal partials (warp per row)
// =====================================================================
__global__ __launch_bounds__(256) void gamma_kernel(float* __restrict__ outp) {
    int w = threadIdx.x >> 5, l = threadIdx.x & 31;
    int R0 = blockIdx.x * 128;  // grid 1024; 128 rows/block; never straddles b
    int rowbase = R0 + w * 16;
    float2* O2 = (float2*)outp;
    float m0 = 0.f, m1 = 0.f;
    for (int i = 0; i < 16; i++) {
        size_t row = (size_t)(rowbase + i);
        float2 a = g_alpha2[row * 32 + l];
        float2 bb = g_beta2[row * 32 + l];
        float gg0 = a.x * bb.x, gg1 = a.y * bb.y;
        float s = gg0 + gg1;
#pragma unroll
        for (int d = 16; d; d >>= 1) s += __shfl_xor_sync(0xffffffffu, s, d);
        float inv = 1.f / s;
        gg0 *= inv; gg1 *= inv;
        O2[row * 32 + l] = make_float2(gg0, gg1);
        m0 += gg0; m1 += gg1;
    }
    int b = R0 >> 12;                       // / 4096
    int chunk = ((R0 & 4095) >> 4) + w;     // [0, 256)
    float* P = g_partial + ((size_t)b * 256 + chunk) * SS;
    P[2 * l] = m0;
    P[2 * l + 1] = m1;
}

// fixed-order reduction over 256 partials per (b, s): deterministic
__global__ void fin_kernel(float* __restrict__ out_marg) {
    int gid = blockIdx.x * 256 + threadIdx.x;  // grid 8 -> 2048 = B*S
    int b = gid >> 6, s = gid & 63;
    const float* P = g_partial + (size_t)b * 256 * SS + s;
    float acc = 0.f;
#pragma unroll 8
    for (int k = 0; k < 256; k++) acc += P[k * SS];
    out_marg[gid] = acc * (1.f / TT);
}

// =====================================================================
extern "C" void kernel_launch(void* const* d_in, const int* in_sizes, int n_in,
                              void* d_out, int out_size) {
    const float* obs     = (const float*)d_in[0];
    const float* W1      = (const float*)d_in[1];
    const float* b1      = (const float*)d_in[2];
    const float* W2      = (const float*)d_in[3];
    const float* b2      = (const float*)d_in[4];
    const float* W3      = (const float*)d_in[5];
    const float* b3      = (const float*)d_in[6];
    const float* logT    = (const float*)d_in[7];
    const float* logInit = (const float*)d_in[8];
    const float* logR    = (const float*)d_in[9];
    const float* logitP  = (const float*)d_in[10];

    float* out = (float*)d_out;
    float* out_sp   = out;                                  // (B,T,S) = 8388608
    float* out_marg = out + (size_t)BB * TT * SS;           // (B,S)   = 2048
    float* out_dur  = out_marg + BB * SS;                   // (S,)    = 64
    float* out_ll   = out_dur + SS;                         // (B,)    = 32

    int smem = SM_FLOATS * 4;  // 173,312 B
    cudaFuncSetAttribute(mlp_kernel, cudaFuncAttributeMaxDynamicSharedMemorySize, smem);

    prep_kernel<<<1, 64>>>(logT, logInit, logR, logitP, out_dur);
    mlp_kernel<<<148, 256, smem>>>(obs, W1, b1, W2, b2, W3, b3);
    recur_kernel<<<64, 32>>>(out_ll);
    gamma_kernel<<<(BB * TT) / 128, 256>>>(out_sp);
    fin_kernel<<<8, 256>>>(out_marg);
}

// round 14
// speedup vs baseline: 1.8160x; 1.6510x over previous
#include <cuda_runtime.h>
#include <cstdint>

#define BB 32
#define TT 4096
#define DD 64
#define HH 128
#define SS 64
#define FEPS 1e-10f

typedef unsigned long long u64;

// ---------------- device scratch (no allocs allowed) ----------------
__device__ float2 g_em2[(size_t)BB * TT * 32];     // emission probs, paired states
__device__ float2 g_alpha2[(size_t)BB * TT * 32];  // forward messages
__device__ float2 g_beta2[(size_t)BB * TT * 32];   // backward messages
__device__ float2 g_Afwd2[32 * 64];  // (A[i][2l], A[i][2l+1]) at [l][i]
__device__ float2 g_Abwd2[32 * 64];  // (A[2l][j], A[2l+1][j]) at [l][j]
__device__ float2 g_pi2[32];
__device__ float  g_partial[(size_t)BB * 256 * SS];  // marginal partials

// ---------------- packed f32x2 helpers ----------------
__device__ __forceinline__ u64 dup2(float x) {
    u64 r; asm("mov.b64 %0, {%1, %1};" : "=l"(r) : "f"(x)); return r;
}
__device__ __forceinline__ void fma2(u64& d, u64 a, u64 b) {
    asm("fma.rn.f32x2 %0, %1, %2, %0;" : "+l"(d) : "l"(a), "l"(b));
}
__device__ __forceinline__ void add2(u64& d, u64 a) {
    asm("add.rn.f32x2 %0, %0, %1;" : "+l"(d) : "l"(a));
}
__device__ __forceinline__ float2 unpk(u64 v) {
    float2 r; asm("mov.b64 {%0, %1}, %2;" : "=f"(r.x), "=f"(r.y) : "l"(v)); return r;
}

// =====================================================================
// 1) prep: transition softmax (+eps), packed A layouts, pi, durations
// =====================================================================
__global__ void prep_kernel(const float* __restrict__ logT,
                            const float* __restrict__ logInit,
                            const float* __restrict__ logR,
                            const float* __restrict__ logitP,
                            float* __restrict__ out_dur) {
    __shared__ float A[SS * SS];
    int tid = threadIdx.x;  // 64 threads
    {
        int i = tid;
        float row[SS];
        float m = -1e30f;
#pragma unroll
        for (int j = 0; j < SS; j++) {
            float v = (j == i) ? -1e10f : logT[i * SS + j];
            row[j] = v; m = fmaxf(m, v);
        }
        float s = 0.f;
#pragma unroll
        for (int j = 0; j < SS; j++) { row[j] = __expf(row[j] - m); s += row[j]; }
        float inv = 1.f / s;
#pragma unroll
        for (int j = 0; j < SS; j++) A[i * SS + j] = fmaf(row[j], inv, FEPS);
    }
    __syncthreads();
    if (tid < 32) {
        int l = tid;
#pragma unroll 4
        for (int i = 0; i < SS; i++) {
            g_Afwd2[l * 64 + i] = make_float2(A[i * SS + 2 * l], A[i * SS + 2 * l + 1]);
            g_Abwd2[l * 64 + i] = make_float2(A[(2 * l) * SS + i], A[(2 * l + 1) * SS + i]);
        }
    }
    if (tid == 0) {
        float m = -1e30f;
        for (int j = 0; j < SS; j++) m = fmaxf(m, logInit[j]);
        float e[SS]; float s = 0.f;
        for (int j = 0; j < SS; j++) { e[j] = __expf(logInit[j] - m); s += e[j]; }
        float inv = 1.f / s;
        for (int j = 0; j < 32; j++)
            g_pi2[j] = make_float2(e[2 * j] * inv, e[2 * j + 1] * inv);
    }
    if (tid < SS) {
        float r = expf(logR[tid]);
        float p = 1.f / (1.f + expf(-logitP[tid]));
        out_dur[tid] = r * (1.f - p) / p;
    }
}

// =====================================================================
// 2) emission MLP (unchanged from R9: persistent, weights in smem)
// =====================================================================
__device__ __forceinline__ float4 relu4(float4 v) {
    return make_float4(fmaxf(v.x, 0.f), fmaxf(v.y, 0.f), fmaxf(v.z, 0.f), fmaxf(v.w, 0.f));
}

#define SM_FLOATS (33088 + 8 * 1280)

__global__ __launch_bounds__(256) void mlp_kernel(
    const float* __restrict__ obs,
    const float* __restrict__ W1, const float* __restrict__ b1,
    const float* __restrict__ W2, const float* __restrict__ b2,
    const float* __restrict__ W3, const float* __restrict__ b3) {
    extern __shared__ float sm[];
    float* W1s = sm;
    float* W2s = sm + 8192;
    float* W3s = sm + 24576;
    float* b1s = sm + 32768;
    float* b2s = sm + 32896;
    float* b3s = sm + 33024;
    float* wbuf = sm + 33088;

    int tid = threadIdx.x, w = tid >> 5, l = tid & 31;

    for (int i = tid; i < 8192 / 4; i += 256) ((float4*)W1s)[i] = ((const float4*)W1)[i];
    for (int i = tid; i < 16384 / 4; i += 256) ((float4*)W2s)[i] = ((const float4*)W2)[i];
    for (int i = tid; i < 8192 / 4; i += 256) ((float4*)W3s)[i] = ((const float4*)W3)[i];
    if (tid < 128) { b1s[tid] = b1[tid]; b2s[tid] = b2[tid]; }
    if (tid < 64) b3s[tid] = b3[tid];
    __syncthreads();

    float* xs = wbuf + w * 1280;
    float* h1 = xs + 256;
    float* h2 = h1 + 512;

    const int nrb = (BB * TT) / 32;
    for (int rb = blockIdx.x; rb < nrb; rb += gridDim.x) {
        int base = rb * 32 + w * 4;
        const float4* ob = (const float4*)(obs + (size_t)base * DD);
        ((float4*)xs)[l] = ob[l];
        ((float4*)xs)[l + 32] = ob[l + 32];
        __syncwarp();

        float4 a0 = ((const float4*)b1s)[l];
        float4 a1 = a0, a2 = a0, a3 = a0;
#pragma unroll 8
        for (int k = 0; k < DD; k++) {
            float4 wv = ((const float4*)W1s)[k * 32 + l];
            float x0 = xs[k], x1 = xs[64 + k], x2 = xs[128 + k], x3 = xs[192 + k];
            a0.x = fmaf(wv.x, x0, a0.x); a0.y = fmaf(wv.y, x0, a0.y);
            a0.z = fmaf(wv.z, x0, a0.z); a0.w = fmaf(wv.w, x0, a0.w);
            a1.x = fmaf(wv.x, x1, a1.x); a1.y = fmaf(wv.y, x1, a1.y);
            a1.z = fmaf(wv.z, x1, a1.z); a1.w = fmaf(wv.w, x1, a1.w);
            a2.x = fmaf(wv.x, x2, a2.x); a2.y = fmaf(wv.y, x2, a2.y);
            a2.z = fmaf(wv.z, x2, a2.z); a2.w = fmaf(wv.w, x2, a2.w);
            a3.x = fmaf(wv.x, x3, a3.x); a3.y = fmaf(wv.y, x3, a3.y);
            a3.z = fmaf(wv.z, x3, a3.z); a3.w = fmaf(wv.w, x3, a3.w);
        }
        ((float4*)h1)[l] = relu4(a0);
        ((float4*)h1)[32 + l] = relu4(a1);
        ((float4*)h1)[64 + l] = relu4(a2);
        ((float4*)h1)[96 + l] = relu4(a3);
        __syncwarp();

        a0 = ((const float4*)b2s)[l];
        a1 = a0; a2 = a0; a3 = a0;
#pragma unroll 8
        for (int k = 0; k < HH; k++) {
            float4 wv = ((const float4*)W2s)[k * 32 + l];
            float x0 = h1[k], x1 = h1[128 + k], x2 = h1[256 + k], x3 = h1[384 + k];
            a0.x = fmaf(wv.x, x0, a0.x); a0.y = fmaf(wv.y, x0, a0.y);
            a0.z = fmaf(wv.z, x0, a0.z); a0.w = fmaf(wv.w, x0, a0.w);
            a1.x = fmaf(wv.x, x1, a1.x); a1.y = fmaf(wv.y, x1, a1.y);
            a1.z = fmaf(wv.z, x1, a1.z); a1.w = fmaf(wv.w, x1, a1.w);
            a2.x = fmaf(wv.x, x2, a2.x); a2.y = fmaf(wv.y, x2, a2.y);
            a2.z = fmaf(wv.z, x2, a2.z); a2.w = fmaf(wv.w, x2, a2.w);
            a3.x = fmaf(wv.x, x3, a3.x); a3.y = fmaf(wv.y, x3, a3.y);
            a3.z = fmaf(wv.z, x3, a3.z); a3.w = fmaf(wv.w, x3, a3.w);
        }
        ((float4*)h2)[l] = relu4(a0);
        ((float4*)h2)[32 + l] = relu4(a1);
        ((float4*)h2)[64 + l] = relu4(a2);
        ((float4*)h2)[96 + l] = relu4(a3);
        __syncwarp();

        float2 c0 = ((const float2*)b3s)[l];
        float2 c1 = c0, c2 = c0, c3 = c0;
#pragma unroll 8
        for (int k = 0; k < HH; k++) {
            float2 wv = ((const float2*)W3s)[k * 32 + l];
            float x0 = h2[k], x1 = h2[128 + k], x2 = h2[256 + k], x3 = h2[384 + k];
            c0.x = fmaf(wv.x, x0, c0.x); c0.y = fmaf(wv.y, x0, c0.y);
            c1.x = fmaf(wv.x, x1, c1.x); c1.y = fmaf(wv.y, x1, c1.y);
            c2.x = fmaf(wv.x, x2, c2.x); c2.y = fmaf(wv.y, x2, c2.y);
            c3.x = fmaf(wv.x, x3, c3.x); c3.y = fmaf(wv.y, x3, c3.y);
        }

        float m0 = fmaxf(c0.x, c0.y), m1 = fmaxf(c1.x, c1.y);
        float m2 = fmaxf(c2.x, c2.y), m3 = fmaxf(c3.x, c3.y);
#pragma unroll
        for (int d = 16; d; d >>= 1) {
            m0 = fmaxf(m0, __shfl_xor_sync(0xffffffffu, m0, d));
            m1 = fmaxf(m1, __shfl_xor_sync(0xffffffffu, m1, d));
            m2 = fmaxf(m2, __shfl_xor_sync(0xffffffffu, m2, d));
            m3 = fmaxf(m3, __shfl_xor_sync(0xffffffffu, m3, d));
        }
        float e00 = __expf(c0.x - m0), e01 = __expf(c0.y - m0);
        float e10 = __expf(c1.x - m1), e11 = __expf(c1.y - m1);
        float e20 = __expf(c2.x - m2), e21 = __expf(c2.y - m2);
        float e30 = __expf(c3.x - m3), e31 = __expf(c3.y - m3);
        float s0 = e00 + e01, s1 = e10 + e11, s2 = e20 + e21, s3 = e30 + e31;
#pragma unroll
        for (int d = 16; d; d >>= 1) {
            s0 += __shfl_xor_sync(0xffffffffu, s0, d);
            s1 += __shfl_xor_sync(0xffffffffu, s1, d);
            s2 += __shfl_xor_sync(0xffffffffu, s2, d);
            s3 += __shfl_xor_sync(0xffffffffu, s3, d);
        }
        float i0 = 1.f / s0, i1 = 1.f / s1, i2 = 1.f / s2, i3 = 1.f / s3;
        g_em2[(size_t)(base + 0) * 32 + l] = make_float2(e00 * i0, e01 * i0);
        g_em2[(size_t)(base + 1) * 32 + l] = make_float2(e10 * i1, e11 * i1);
        g_em2[(size_t)(base + 2) * 32 + l] = make_float2(e20 * i2, e21 * i2);
        g_em2[(size_t)(base + 3) * 32 + l] = make_float2(e30 * i3, e31 * i3);
    }
}

// =====================================================================
// 3) recursions v2: 4 warps per (b,dir); i-dim split 16 terms/warp,
//    4 accumulators, double-buffered smem partials, 1 bar/step,
//    4-deep emission prefetch, renorm every 4 steps (LL tracks scale).
// =====================================================================

// shared matvec: 16 fma2 into 4 accs, combine, exchange partials, total in s
#define RMATVEC(T)                                                              \
    u64 ac0 = 0, ac1 = 0, ac2 = 0, ac3 = 0;                                     \
    _Pragma("unroll") for (int j = 0; j < 8; j++) {                             \
        ulonglong2 v = buf2[8 * w + j];                                         \
        if ((j & 1) == 0) { fma2(ac0, cp[2 * j], v.x); fma2(ac1, cp[2 * j + 1], v.y); } \
        else              { fma2(ac2, cp[2 * j], v.x); fma2(ac3, cp[2 * j + 1], v.y); } \
    }                                                                           \
    add2(ac0, ac1); add2(ac2, ac3); add2(ac0, ac2);                             \
    sp[(T) & 1][w * 32 + l] = ac0;                                              \
    __syncthreads();                                                            \
    u64 s = sp[(T) & 1][l];       add2(s, sp[(T) & 1][32 + l]);                 \
    u64 s2 = sp[(T) & 1][64 + l]; add2(s2, sp[(T) & 1][96 + l]);                \
    add2(s, s2);

#define FSTEP(T, EV, RN) {                                                      \
    RMATVEC(T)                                                                  \
    float2 sv = unpk(s);                                                        \
    a0 = sv.x * ((EV).x + FEPS); a1 = sv.y * ((EV).y + FEPS);                   \
    if (w == 0) AL[(size_t)(T) * 32] = make_float2(a0, a1);                     \
    if (RN) {                                                                   \
        float sum = a0 + a1;                                                    \
        _Pragma("unroll") for (int d = 16; d; d >>= 1)                          \
            sum += __shfl_xor_sync(0xffffffffu, sum, d);                        \
        float inv = 1.f / sum; a0 *= inv; a1 *= inv;                            \
        if (w == 0) c += (double)__logf(sum);                                   \
    }                                                                           \
    if ((l >> 3) == w) buf2[l] = make_ulonglong2(dup2(a0), dup2(a1));           \
    __syncwarp(); }

#define BSTEP(T, EV, RN) {                                                      \
    RMATVEC(T)                                                                  \
    float2 sv = unpk(s);                                                        \
    float b0 = sv.x, b1 = sv.y;                                                 \
    if (w == 0) BL[(size_t)(T) * 32] = make_float2(b0, b1);                     \
    if (RN) {                                                                   \
        float sum = b0 + b1;                                                    \
        _Pragma("unroll") for (int d = 16; d; d >>= 1)                          \
            sum += __shfl_xor_sync(0xffffffffu, sum, d);                        \
        float inv = 1.f / sum; b0 *= inv; b1 *= inv;                            \
    }                                                                           \
    float v0 = b0 * ((EV).x + FEPS), v1 = b1 * ((EV).y + FEPS);                 \
    if ((l >> 3) == w) buf2[l] = make_ulonglong2(dup2(v0), dup2(v1));           \
    __syncwarp(); }

__global__ __launch_bounds__(128) void recur_kernel(float* __restrict__ d_ll) {
    int id = blockIdx.x;  // 64 = 32 batches x 2 directions
    int b = id >> 1;
    bool bwd = (id & 1) != 0;
    int tid = threadIdx.x, w = tid >> 5, l = tid & 31;

    __shared__ __align__(16) ulonglong2 buf2[32];  // dup-pair message buffer
    __shared__ u64 sp[2][128];                     // double-buffered partials

    u64 cp[16];  // this warp's 16 A-column pairs for lane l
    const u64* M = (const u64*)(bwd ? g_Abwd2 : g_Afwd2) + (size_t)l * 64 + 16 * w;
#pragma unroll
    for (int k = 0; k < 16; k++) cp[k] = M[k];

    const float2* E = g_em2 + (size_t)b * TT * 32 + l;

    if (!bwd) {
        float2* AL = g_alpha2 + (size_t)b * TT * 32 + l;
        float2 pp = g_pi2[l];
        float2 e0 = E[0];
        float a0 = pp.x * e0.x, a1 = pp.y * e0.y;  // t=0: NO eps (matches ref)
        if (w == 0) AL[0] = make_float2(a0, a1);
        if ((l >> 3) == w) buf2[l] = make_ulonglong2(dup2(a0), dup2(a1));
        __syncwarp();
        double c = 0.0;
        float2 eA0 = E[32], eA1 = E[64], eA2 = E[96], eA3 = E[128];
        for (int t0 = 1; t0 + 7 < TT; t0 += 4) {
            float2 eB0 = E[(size_t)(t0 + 4) * 32], eB1 = E[(size_t)(t0 + 5) * 32];
            float2 eB2 = E[(size_t)(t0 + 6) * 32], eB3 = E[(size_t)(t0 + 7) * 32];
            FSTEP(t0, eA0, 0)
            FSTEP(t0 + 1, eA1, 0)
            FSTEP(t0 + 2, eA2, 0)
            FSTEP(t0 + 3, eA3, 1)
            eA0 = eB0; eA1 = eB1; eA2 = eB2; eA3 = eB3;
        }
        // after loop: t0 == 4089; eA holds E[4089..4092]
        FSTEP(4089, eA0, 0)
        FSTEP(4090, eA1, 0)
        FSTEP(4091, eA2, 0)
        FSTEP(4092, eA3, 1)
        float2 ex = E[(size_t)4093 * 32];
        FSTEP(4093, ex, 0)
        ex = E[(size_t)4094 * 32];
        FSTEP(4094, ex, 0)
        ex = E[(size_t)4095 * 32];
        FSTEP(4095, ex, 0)
        float sum = a0 + a1;
#pragma unroll
        for (int d = 16; d; d >>= 1) sum += __shfl_xor_sync(0xffffffffu, sum, d);
        if (w == 0 && l == 0) d_ll[b] = __logf(sum) + (float)c;
    } else {
        float2* BL = g_beta2 + (size_t)b * TT * 32 + l;
        float2 eL = E[(size_t)(TT - 1) * 32];
        if (w == 0) BL[(size_t)(TT - 1) * 32] = make_float2(1.f, 1.f);
        float vI0 = eL.x + FEPS, vI1 = eL.y + FEPS;
        if ((l >> 3) == w) buf2[l] = make_ulonglong2(dup2(vI0), dup2(vI1));
        __syncwarp();
        float2 eA0 = E[(size_t)4094 * 32], eA1 = E[(size_t)4093 * 32];
        float2 eA2 = E[(size_t)4092 * 32], eA3 = E[(size_t)4091 * 32];
        for (int t0 = 4094; t0 - 7 >= 0; t0 -= 4) {
            float2 eB0 = E[(size_t)(t0 - 4) * 32], eB1 = E[(size_t)(t0 - 5) * 32];
            float2 eB2 = E[(size_t)(t0 - 6) * 32], eB3 = E[(size_t)(t0 - 7) * 32];
            BSTEP(t0, eA0, 0)
            BSTEP(t0 - 1, eA1, 0)
            BSTEP(t0 - 2, eA2, 0)
            BSTEP(t0 - 3, eA3, 1)
            eA0 = eB0; eA1 = eB1; eA2 = eB2; eA3 = eB3;
        }
        // after loop: t0 == 6; eA holds E[6,5,4,3]
        BSTEP(6, eA0, 0)
        BSTEP(5, eA1, 0)
        BSTEP(4, eA2, 0)
        BSTEP(3, eA3, 1)
        float2 ex = E[(size_t)2 * 32];
        BSTEP(2, ex, 0)
        ex = E[32];
        BSTEP(1, ex, 0)
        ex = E[0];
        BSTEP(0, ex, 0)
    }
}

// =====================================================================
// 4) gamma + deterministic marginal partials (warp per row)
// =====================================================================
__global__ __launch_bounds__(256) void gamma_kernel(float* __restrict__ outp) {
    int w = threadIdx.x >> 5, l = threadIdx.x & 31;
    int R0 = blockIdx.x * 128;
    int rowbase = R0 + w * 16;
    float2* O2 = (float2*)outp;
    float m0 = 0.f, m1 = 0.f;
    for (int i = 0; i < 16; i++) {
        size_t row = (size_t)(rowbase + i);
        float2 a = g_alpha2[row * 32 + l];
        float2 bb = g_beta2[row * 32 + l];
        float gg0 = a.x * bb.x, gg1 = a.y * bb.y;
        float s = gg0 + gg1;
#pragma unroll
        for (int d = 16; d; d >>= 1) s += __shfl_xor_sync(0xffffffffu, s, d);
        float inv = 1.f / s;
        gg0 *= inv; gg1 *= inv;
        O2[row * 32 + l] = make_float2(gg0, gg1);
        m0 += gg0; m1 += gg1;
    }
    int b = R0 >> 12;
    int chunk = ((R0 & 4095) >> 4) + w;
    float* P = g_partial + ((size_t)b * 256 + chunk) * SS;
    P[2 * l] = m0;
    P[2 * l + 1] = m1;
}

__global__ void fin_kernel(float* __restrict__ out_marg) {
    int gid = blockIdx.x * 256 + threadIdx.x;
    int b = gid >> 6, s = gid & 63;
    const float* P = g_partial + (size_t)b * 256 * SS + s;
    float acc = 0.f;
#pragma unroll 8
    for (int k = 0; k < 256; k++) acc += P[k * SS];
    out_marg[gid] = acc * (1.f / TT);
}

// =====================================================================
extern "C" void kernel_launch(void* const* d_in, const int* in_sizes, int n_in,
                              void* d_out, int out_size) {
    const float* obs     = (const float*)d_in[0];
    const float* W1      = (const float*)d_in[1];
    const float* b1      = (const float*)d_in[2];
    const float* W2      = (const float*)d_in[3];
    const float* b2      = (const float*)d_in[4];
    const float* W3      = (const float*)d_in[5];
    const float* b3      = (const float*)d_in[6];
    const float* logT    = (const float*)d_in[7];
    const float* logInit = (const float*)d_in[8];
    const float* logR    = (const float*)d_in[9];
    const float* logitP  = (const float*)d_in[10];

    float* out = (float*)d_out;
    float* out_sp   = out;                         // (B,T,S)
    float* out_marg = out + (size_t)BB * TT * SS;  // (B,S)
    float* out_dur  = out_marg + BB * SS;          // (S,)
    float* out_ll   = out_dur + SS;                // (B,)

    int smem = SM_FLOATS * 4;
    cudaFuncSetAttribute(mlp_kernel, cudaFuncAttributeMaxDynamicSharedMemorySize, smem);

    prep_kernel<<<1, 64>>>(logT, logInit, logR, logitP, out_dur);
    mlp_kernel<<<148, 256, smem>>>(obs, W1, b1, W2, b2, W3, b3);
    recur_kernel<<<64, 128>>>(out_ll);
    gamma_kernel<<<(BB * TT) / 128, 256>>>(out_sp);
    fin_kernel<<<8, 256>>>(out_marg);
}